// round 2
// baseline (speedup 1.0000x reference)
#include <cuda_runtime.h>
#include <cstdint>

// Problem constants
#define BH_   64      // B*H = 4*16
#define M_    64      // number of blocks m = N/b
#define BB_   128     // block size b
#define D_    64      // head dim
#define N_    8192
#define SCALE_ 0.125f // 1/sqrt(64)
#define EPS_   1e-6f
#define NSTEPS_ 3

// Scratch (device globals; no allocation allowed)
// KBAR: [bh][l][k][d]   (contiguous per (bh,l) slice for kl_kernel reads)
// QBAR: [bh][k][l][d]   (contiguous per (bh,k) slice for kr_kernel reads)
// LBUF: [bh][l][i][k]
// VBAR: [bh][l][k][d]
__device__ float g_KBAR[(size_t)BH_*BB_*M_*D_];
__device__ float g_QBAR[(size_t)BH_*M_*BB_*D_];
__device__ float g_LBUF[(size_t)BH_*BB_*M_*M_];
__device__ float g_VBAR[(size_t)BH_*BB_*M_*D_];

// ---------------------------------------------------------------------------
// Kernel 1: Kbar init = broadcast mean over l' of K block k
// grid (M_, BH_), 256 threads
// ---------------------------------------------------------------------------
__global__ __launch_bounds__(256)
void init_kbar_kernel(const float* __restrict__ K)
{
    int k  = blockIdx.x;
    int bh = blockIdx.y;
    int tid = threadIdx.x;
    int d = tid & 63;
    int g = tid >> 6;          // 0..3

    __shared__ float red[4][64];

    const float* Kg = K + ((size_t)bh * N_ + (size_t)k * BB_) * D_;
    float s = 0.f;
    for (int lp = g; lp < BB_; lp += 4)
        s += Kg[(size_t)lp * D_ + d];
    red[g][d] = s;
    __syncthreads();

    __shared__ float meanv[64];
    if (tid < 64) {
        meanv[tid] = (red[0][tid] + red[1][tid] + red[2][tid] + red[3][tid]) * (1.0f / BB_);
    }
    __syncthreads();

    float mv = meanv[d];
    float* dst = g_KBAR + ((size_t)bh * BB_ * M_ + (size_t)k) * D_; // + l*M_*D_
    for (int l = g; l < BB_; l += 4)
        dst[(size_t)l * M_ * D_ + d] = mv;
}

// ---------------------------------------------------------------------------
// Kernel 2: per (bh, l):
//   scores = scale * Q_l (64xD) @ Kbar_l^T (Dx64); L = softmax_k(scores)
//   w[k] = sum_i L[i][k];  Qbar[k][d] = (L^T @ Q_l)[k][d] / (w[k]+eps)
//   optionally write L to global (last iteration)
// grid (BB_, BH_), 256 threads, register tile 4x4
// ---------------------------------------------------------------------------
__global__ __launch_bounds__(256)
void kl_kernel(const float* __restrict__ Q, int writeL)
{
    int l  = blockIdx.x;
    int bh = blockIdx.y;
    int tid = threadIdx.x;

    __shared__ float Qs[M_ * 65];    // Qs[i][d], pitch 65
    __shared__ float KsS[M_ * 65];   // first Kbar_l[k][d], later L[i][k]
    __shared__ float wsh[M_];

    // Load Q_l: Q[bh, i*BB_+l, d]
    const float* Qg = Q + (size_t)bh * N_ * D_ + (size_t)l * D_;
    for (int idx = tid; idx < M_ * D_; idx += 256) {
        int i = idx >> 6, d = idx & 63;
        Qs[i * 65 + d] = Qg[(size_t)i * BB_ * D_ + d];
    }
    // Load Kbar_l (contiguous)
    const float* Kg = g_KBAR + ((size_t)bh * BB_ + l) * M_ * D_;
    for (int idx = tid; idx < M_ * D_; idx += 256) {
        int kk = idx >> 6, d = idx & 63;
        KsS[kk * 65 + d] = Kg[idx];
    }
    __syncthreads();

    int ty = tid >> 4;   // 0..15 -> rows i = ty*4+a
    int tx = tid & 15;   // 0..15 -> cols k = tx*4+c

    float acc[4][4];
#pragma unroll
    for (int a = 0; a < 4; a++)
#pragma unroll
        for (int c = 0; c < 4; c++) acc[a][c] = 0.f;

    for (int d = 0; d < D_; d++) {
        float q[4], kv[4];
#pragma unroll
        for (int a = 0; a < 4; a++) q[a] = Qs[(ty * 4 + a) * 65 + d];
#pragma unroll
        for (int c = 0; c < 4; c++) kv[c] = KsS[(tx * 4 + c) * 65 + d];
#pragma unroll
        for (int a = 0; a < 4; a++)
#pragma unroll
            for (int c = 0; c < 4; c++) acc[a][c] += q[a] * kv[c];
    }

    // softmax over k; each row i is owned by a 16-lane half-warp segment
    float Lreg[4][4];
#pragma unroll
    for (int a = 0; a < 4; a++) {
        float mx = -1e30f;
#pragma unroll
        for (int c = 0; c < 4; c++) { acc[a][c] *= SCALE_; mx = fmaxf(mx, acc[a][c]); }
#pragma unroll
        for (int off = 8; off >= 1; off >>= 1)
            mx = fmaxf(mx, __shfl_xor_sync(0xffffffffu, mx, off, 16));
        float ssum = 0.f;
#pragma unroll
        for (int c = 0; c < 4; c++) { float e = __expf(acc[a][c] - mx); Lreg[a][c] = e; ssum += e; }
#pragma unroll
        for (int off = 8; off >= 1; off >>= 1)
            ssum += __shfl_xor_sync(0xffffffffu, ssum, off, 16);
        float inv = 1.0f / ssum;
#pragma unroll
        for (int c = 0; c < 4; c++) Lreg[a][c] *= inv;
    }

    __syncthreads();   // done reading KsS as Kbar
    // store L into KsS[i][k]
#pragma unroll
    for (int a = 0; a < 4; a++)
#pragma unroll
        for (int c = 0; c < 4; c++)
            KsS[(ty * 4 + a) * 65 + tx * 4 + c] = Lreg[a][c];
    __syncthreads();

    // w[k] = sum_i L[i][k];  store 1/(w+eps)
    if (tid < M_) {
        float s = 0.f;
#pragma unroll 8
        for (int i = 0; i < M_; i++) s += KsS[i * 65 + tid];
        wsh[tid] = 1.0f / (s + EPS_);
    }

    if (writeL) {
        float* Lg = g_LBUF + ((size_t)bh * BB_ + l) * M_ * M_;
#pragma unroll
        for (int a = 0; a < 4; a++) {
            float4 v = make_float4(Lreg[a][0], Lreg[a][1], Lreg[a][2], Lreg[a][3]);
            *(float4*)(Lg + (size_t)(ty * 4 + a) * M_ + tx * 4) = v;
        }
    }
    __syncthreads();

    // Qbar[k][d] = sum_i L[i][k] * Q[i][d], normalized by wsh[k]
    float acc2[4][4];
#pragma unroll
    for (int a = 0; a < 4; a++)
#pragma unroll
        for (int c = 0; c < 4; c++) acc2[a][c] = 0.f;

    for (int i = 0; i < M_; i++) {
        float lv[4], q[4];
#pragma unroll
        for (int a = 0; a < 4; a++) lv[a] = KsS[i * 65 + ty * 4 + a];  // k = ty*4+a
#pragma unroll
        for (int c = 0; c < 4; c++) q[c] = Qs[i * 65 + tx * 4 + c];    // d = tx*4+c
#pragma unroll
        for (int a = 0; a < 4; a++)
#pragma unroll
            for (int c = 0; c < 4; c++) acc2[a][c] += lv[a] * q[c];
    }

    float* Qbg = g_QBAR + (size_t)bh * M_ * BB_ * D_ + (size_t)l * D_;
#pragma unroll
    for (int a = 0; a < 4; a++) {
        int kk = ty * 4 + a;
        float wi = wsh[kk];
        float4 v = make_float4(acc2[a][0] * wi, acc2[a][1] * wi,
                               acc2[a][2] * wi, acc2[a][3] * wi);
        *(float4*)(Qbg + (size_t)kk * BB_ * D_ + tx * 4) = v;
    }
}

// ---------------------------------------------------------------------------
// Kernel 3: per (bh, k):
//   scores = scale * Qbar_k (128xD) @ K_k^T (Dx128); R = softmax_{l'}(scores)
//   Kbar[l][d] = R @ K_k      (normal iterations)
//   Vbar[l][d] = R @ V_k      (last iteration)
// grid (M_, BH_), 256 threads, dynamic smem, 8x8 register tiles for scores
// ---------------------------------------------------------------------------
#define KR_SMEM_FLOATS (2 * BB_ * 65 + BB_ * 129)
#define KR_SMEM_BYTES  (KR_SMEM_FLOATS * 4)

__global__ __launch_bounds__(256)
void kr_kernel(const float* __restrict__ K, const float* __restrict__ V, int last)
{
    extern __shared__ float sm[];
    float* Qbs = sm;                 // [BB_][65]  (reused for V on last iter)
    float* Ks  = sm + BB_ * 65;      // [BB_][65]
    float* Rs  = sm + 2 * BB_ * 65;  // [BB_][129]

    int k  = blockIdx.x;
    int bh = blockIdx.y;
    int tid = threadIdx.x;

    const float* Qbg = g_QBAR + ((size_t)bh * M_ + k) * BB_ * D_;
    for (int idx = tid; idx < BB_ * D_; idx += 256) {
        int l = idx >> 6, d = idx & 63;
        Qbs[l * 65 + d] = Qbg[idx];
    }
    const float* Kg = K + ((size_t)bh * N_ + (size_t)k * BB_) * D_;
    for (int idx = tid; idx < BB_ * D_; idx += 256) {
        int l = idx >> 6, d = idx & 63;
        Ks[l * 65 + d] = Kg[idx];
    }
    __syncthreads();

    int ty = tid >> 4;  // rows l  = ty*8+a
    int tx = tid & 15;  // cols l' = tx*8+c

    float acc[8][8];
#pragma unroll
    for (int a = 0; a < 8; a++)
#pragma unroll
        for (int c = 0; c < 8; c++) acc[a][c] = 0.f;

    for (int d = 0; d < D_; d++) {
        float q[8], kk8[8];
#pragma unroll
        for (int a = 0; a < 8; a++) q[a] = Qbs[(ty * 8 + a) * 65 + d];
#pragma unroll
        for (int c = 0; c < 8; c++) kk8[c] = Ks[(tx * 8 + c) * 65 + d];
#pragma unroll
        for (int a = 0; a < 8; a++)
#pragma unroll
            for (int c = 0; c < 8; c++) acc[a][c] += q[a] * kk8[c];
    }

    // softmax over l' (row spread over a 16-lane segment), write R into Rs
#pragma unroll
    for (int a = 0; a < 8; a++) {
        float mx = -1e30f;
#pragma unroll
        for (int c = 0; c < 8; c++) { acc[a][c] *= SCALE_; mx = fmaxf(mx, acc[a][c]); }
#pragma unroll
        for (int off = 8; off >= 1; off >>= 1)
            mx = fmaxf(mx, __shfl_xor_sync(0xffffffffu, mx, off, 16));
        float ssum = 0.f;
#pragma unroll
        for (int c = 0; c < 8; c++) { float e = __expf(acc[a][c] - mx); acc[a][c] = e; ssum += e; }
#pragma unroll
        for (int off = 8; off >= 1; off >>= 1)
            ssum += __shfl_xor_sync(0xffffffffu, ssum, off, 16);
        float inv = 1.0f / ssum;
#pragma unroll
        for (int c = 0; c < 8; c++)
            Rs[(ty * 8 + a) * 129 + tx * 8 + c] = acc[a][c] * inv;
    }
    __syncthreads();

    const float* Op = Ks;
    if (last) {
        const float* Vg = V + ((size_t)bh * N_ + (size_t)k * BB_) * D_;
        for (int idx = tid; idx < BB_ * D_; idx += 256) {
            int l = idx >> 6, d = idx & 63;
            Qbs[l * 65 + d] = Vg[idx];
        }
        __syncthreads();
        Op = Qbs;
    }

    // out2[l][d] = sum_{l'} R[l][l'] * Op[l'][d] ; 128x64 output, 8x4 per thread
    float acc2[8][4];
#pragma unroll
    for (int a = 0; a < 8; a++)
#pragma unroll
        for (int c = 0; c < 4; c++) acc2[a][c] = 0.f;

    for (int lp = 0; lp < BB_; lp++) {
        float r[8], o[4];
#pragma unroll
        for (int a = 0; a < 8; a++) r[a] = Rs[(ty * 8 + a) * 129 + lp];
#pragma unroll
        for (int c = 0; c < 4; c++) o[c] = Op[lp * 65 + tx * 4 + c];
#pragma unroll
        for (int a = 0; a < 8; a++)
#pragma unroll
            for (int c = 0; c < 4; c++) acc2[a][c] += r[a] * o[c];
    }

    float* dst = (last ? g_VBAR : g_KBAR) + ((size_t)bh * BB_ * M_ + (size_t)k) * D_;
#pragma unroll
    for (int a = 0; a < 8; a++) {
        int l = ty * 8 + a;
        float4 v = make_float4(acc2[a][0], acc2[a][1], acc2[a][2], acc2[a][3]);
        *(float4*)(dst + (size_t)l * M_ * D_ + tx * 4) = v;
    }
}

// ---------------------------------------------------------------------------
// Kernel 4: per (bh, l): out[i][d] = sum_k L[i][k] * Vbar[k][d]
// grid (BB_, BH_), 256 threads, 4x4 tiles
// ---------------------------------------------------------------------------
__global__ __launch_bounds__(256)
void out_kernel(float* __restrict__ O)
{
    int l  = blockIdx.x;
    int bh = blockIdx.y;
    int tid = threadIdx.x;

    __shared__ float Ls[M_ * 65];
    __shared__ float Vbs[M_ * 65];

    const float* Lg = g_LBUF + ((size_t)bh * BB_ + l) * M_ * M_;
    for (int idx = tid; idx < M_ * M_; idx += 256) {
        int i = idx >> 6, kk = idx & 63;
        Ls[i * 65 + kk] = Lg[idx];
    }
    const float* Vg = g_VBAR + ((size_t)bh * BB_ + l) * M_ * D_;
    for (int idx = tid; idx < M_ * D_; idx += 256) {
        int kk = idx >> 6, d = idx & 63;
        Vbs[kk * 65 + d] = Vg[idx];
    }
    __syncthreads();

    int ty = tid >> 4;  // rows i = ty*4+a
    int tx = tid & 15;  // cols d = tx*4+c

    float acc[4][4];
#pragma unroll
    for (int a = 0; a < 4; a++)
#pragma unroll
        for (int c = 0; c < 4; c++) acc[a][c] = 0.f;

    for (int kk = 0; kk < M_; kk++) {
        float lv[4], vv[4];
#pragma unroll
        for (int a = 0; a < 4; a++) lv[a] = Ls[(ty * 4 + a) * 65 + kk];
#pragma unroll
        for (int c = 0; c < 4; c++) vv[c] = Vbs[kk * 65 + tx * 4 + c];
#pragma unroll
        for (int a = 0; a < 4; a++)
#pragma unroll
            for (int c = 0; c < 4; c++) acc[a][c] += lv[a] * vv[c];
    }

    float* Og = O + (size_t)bh * N_ * D_ + (size_t)l * D_;
#pragma unroll
    for (int a = 0; a < 4; a++) {
        int i = ty * 4 + a;
        float4 v = make_float4(acc[a][0], acc[a][1], acc[a][2], acc[a][3]);
        *(float4*)(Og + (size_t)i * BB_ * D_ + tx * 4) = v;
    }
}

// ---------------------------------------------------------------------------
extern "C" void kernel_launch(void* const* d_in, const int* in_sizes, int n_in,
                              void* d_out, int out_size)
{
    const float* Q = (const float*)d_in[0];
    const float* K = (const float*)d_in[1];
    const float* V = (const float*)d_in[2];
    float* O = (float*)d_out;

    // Attribute set (not a stream op; capture-safe, idempotent)
    cudaFuncSetAttribute(kr_kernel, cudaFuncAttributeMaxDynamicSharedMemorySize,
                         KR_SMEM_BYTES);

    dim3 blk(256);
    init_kbar_kernel<<<dim3(M_, BH_), blk>>>(K);
    for (int t = 0; t < NSTEPS_; t++) {
        int lastFlag = (t == NSTEPS_ - 1) ? 1 : 0;
        kl_kernel<<<dim3(BB_, BH_), blk>>>(Q, lastFlag);
        kr_kernel<<<dim3(M_, BH_), blk, KR_SMEM_BYTES>>>(K, V, lastFlag);
    }
    out_kernel<<<dim3(BB_, BH_), blk>>>(O);
}

// round 7
// speedup vs baseline: 2.9531x; 2.9531x over previous
#include <cuda_runtime.h>
#include <cstdint>

// Problem constants
#define BH_   64      // B*H = 4*16
#define M_    64      // number of blocks m = N/b
#define BB_   128     // block size b
#define D_    64      // head dim
#define N_    8192
#define SCALE_ 0.125f // 1/sqrt(64)
#define EPS_   1e-6f
#define NSTEPS_ 3

// Scratch (device globals; no allocation allowed)
// KBAR: [bh][l][k][d]   (contiguous per (bh,l) slice for kl_kernel reads)
// QBAR: [bh][k][l][d]   (contiguous per (bh,k) slice for kr_kernel reads)
// LBUF: [bh][l][i][k]
// VBAR: [bh][l][k][d]
__device__ float g_KBAR[(size_t)BH_*BB_*M_*D_];
__device__ float g_QBAR[(size_t)BH_*M_*BB_*D_];
__device__ float g_LBUF[(size_t)BH_*BB_*M_*M_];
__device__ float g_VBAR[(size_t)BH_*BB_*M_*D_];

// ---------------------------------------------------------------------------
// tf32 mma helpers  (m16n8k8, A row-major, B col-major, fp32 accum)
// A frag: a0:(g,t) a1:(g+8,t) a2:(g,t+4) a3:(g+8,t+4)   [g=lane>>2, t=lane&3]
// B frag: b0:(t,g) b1:(t+4,g)  (row = k-dim, col = n-dim)
// C frag: c0:(g,2t) c1:(g,2t+1) c2:(g+8,2t) c3:(g+8,2t+1)
// ---------------------------------------------------------------------------
__device__ __forceinline__ uint32_t f2tf(float x){
    uint32_t r; asm("cvt.rna.tf32.f32 %0, %1;" : "=r"(r) : "f"(x)); return r;
}
__device__ __forceinline__ void mma8(float* c,
    uint32_t a0, uint32_t a1, uint32_t a2, uint32_t a3,
    uint32_t b0, uint32_t b1)
{
    asm volatile("mma.sync.aligned.m16n8k8.row.col.f32.tf32.tf32.f32 "
        "{%0,%1,%2,%3},{%4,%5,%6,%7},{%8,%9},{%0,%1,%2,%3};"
        : "+f"(c[0]), "+f"(c[1]), "+f"(c[2]), "+f"(c[3])
        : "r"(a0), "r"(a1), "r"(a2), "r"(a3), "r"(b0), "r"(b1));
}

// ---------------------------------------------------------------------------
// Kernel 1: Kbar init = broadcast mean over l' of K block k
// ---------------------------------------------------------------------------
__global__ __launch_bounds__(256)
void init_kbar_kernel(const float* __restrict__ K)
{
    int k  = blockIdx.x;
    int bh = blockIdx.y;
    int tid = threadIdx.x;
    int d = tid & 63;
    int g = tid >> 6;          // 0..3

    __shared__ float red[4][64];

    const float* Kg = K + ((size_t)bh * N_ + (size_t)k * BB_) * D_;
    float s = 0.f;
    for (int lp = g; lp < BB_; lp += 4)
        s += Kg[(size_t)lp * D_ + d];
    red[g][d] = s;
    __syncthreads();

    __shared__ float meanv[64];
    if (tid < 64) {
        meanv[tid] = (red[0][tid] + red[1][tid] + red[2][tid] + red[3][tid]) * (1.0f / BB_);
    }
    __syncthreads();

    float mv = meanv[d];
    float* dst = g_KBAR + ((size_t)bh * BB_ * M_ + (size_t)k) * D_; // + l*M_*D_
    for (int l = g; l < BB_; l += 4)
        dst[(size_t)l * M_ * D_ + d] = mv;
}

// ---------------------------------------------------------------------------
// Kernel 2 (tensor): per (bh, l):
//   S = scale * Q_l (64x64) @ Kbar_l^T ; L = softmax_k(S)
//   Qbar[k][d] = (L^T @ Q_l)[k][d] / (w[k]+eps)
// grid (128, 64), 256 threads (8 warps: 4 row-groups x 2 col-groups)
// ---------------------------------------------------------------------------
#define KL_PQ 72
#define KL_PK 68
#define KL_PL 72
#define KL_SMEM_FLOATS (64*KL_PQ + 64*KL_PK + 64*KL_PL + 64)
#define KL_SMEM_BYTES  (KL_SMEM_FLOATS * 4)

__global__ __launch_bounds__(256, 4)
void kl_kernel(const float* __restrict__ Q, int writeL)
{
    extern __shared__ float sm[];
    float* Qs  = sm;                         // [64][72]
    float* Ks  = Qs + 64 * KL_PQ;            // [64][68]  Kbar_l
    float* Ls  = Ks + 64 * KL_PK;            // [64][72]  scores -> L
    float* wsh = Ls + 64 * KL_PL;            // [64]

    int l  = blockIdx.x;
    int bh = blockIdx.y;
    int tid = threadIdx.x;
    int lane = tid & 31, wid = tid >> 5;
    int g = lane >> 2, t = lane & 3;

    // Load Q_l rows (strided in gmem) and Kbar_l (contiguous), float4
    const float* Qg = Q + (size_t)bh * N_ * D_ + (size_t)l * D_;
    for (int idx = tid; idx < 64 * 16; idx += 256) {
        int i = idx >> 4, d4 = idx & 15;
        float4 v = *(const float4*)(Qg + (size_t)i * BB_ * D_ + d4 * 4);
        float* p = Qs + i * KL_PQ + d4 * 4;
        p[0] = v.x; p[1] = v.y; p[2] = v.z; p[3] = v.w;
    }
    const float* Kg = g_KBAR + ((size_t)bh * BB_ + l) * M_ * D_;
    for (int idx = tid; idx < 64 * 16; idx += 256) {
        int kk = idx >> 4, d4 = idx & 15;
        float4 v = *(const float4*)(Kg + idx * 4);
        float* p = Ks + kk * KL_PK + d4 * 4;
        p[0] = v.x; p[1] = v.y; p[2] = v.z; p[3] = v.w;
    }
    __syncthreads();

    int wr = wid >> 1, wc = wid & 1;
    int m0 = wr * 16;

    // GEMM1: S[i][k] = sum_d Q[i][d] * Kbar[k][d]
    float acc[4][4];
#pragma unroll
    for (int nt = 0; nt < 4; nt++)
#pragma unroll
        for (int e = 0; e < 4; e++) acc[nt][e] = 0.f;

#pragma unroll
    for (int s = 0; s < 8; s++) {
        int k0 = s * 8;
        uint32_t a0 = f2tf(Qs[(m0 + g    ) * KL_PQ + k0 + t    ]);
        uint32_t a1 = f2tf(Qs[(m0 + g + 8) * KL_PQ + k0 + t    ]);
        uint32_t a2 = f2tf(Qs[(m0 + g    ) * KL_PQ + k0 + t + 4]);
        uint32_t a3 = f2tf(Qs[(m0 + g + 8) * KL_PQ + k0 + t + 4]);
#pragma unroll
        for (int nt = 0; nt < 4; nt++) {
            int n0 = wc * 32 + nt * 8;
            uint32_t b0 = f2tf(Ks[(n0 + g) * KL_PK + k0 + t    ]);
            uint32_t b1 = f2tf(Ks[(n0 + g) * KL_PK + k0 + t + 4]);
            mma8(acc[nt], a0, a1, a2, a3, b0, b1);
        }
    }

    // scaled scores -> Ls (distinct buffer; safe without pre-sync)
#pragma unroll
    for (int nt = 0; nt < 4; nt++) {
        int n0 = wc * 32 + nt * 8;
        Ls[(m0 + g    ) * KL_PL + n0 + 2 * t    ] = acc[nt][0] * SCALE_;
        Ls[(m0 + g    ) * KL_PL + n0 + 2 * t + 1] = acc[nt][1] * SCALE_;
        Ls[(m0 + g + 8) * KL_PL + n0 + 2 * t    ] = acc[nt][2] * SCALE_;
        Ls[(m0 + g + 8) * KL_PL + n0 + 2 * t + 1] = acc[nt][3] * SCALE_;
    }
    __syncthreads();

    // softmax over k: 4 threads per row (16 elements each), shfl groups of 4
    {
        int row = tid >> 2, q = tid & 3;
        float* rp = Ls + row * KL_PL + q * 16;
        float vv[16];
#pragma unroll
        for (int j = 0; j < 4; j++) *(float4*)(vv + 4 * j) = *(float4*)(rp + 4 * j);
        float mx = -1e30f;
#pragma unroll
        for (int j = 0; j < 16; j++) mx = fmaxf(mx, vv[j]);
        mx = fmaxf(mx, __shfl_xor_sync(0xffffffffu, mx, 1));
        mx = fmaxf(mx, __shfl_xor_sync(0xffffffffu, mx, 2));
        float ssum = 0.f;
#pragma unroll
        for (int j = 0; j < 16; j++) { vv[j] = __expf(vv[j] - mx); ssum += vv[j]; }
        ssum += __shfl_xor_sync(0xffffffffu, ssum, 1);
        ssum += __shfl_xor_sync(0xffffffffu, ssum, 2);
        float inv = 1.0f / ssum;
#pragma unroll
        for (int j = 0; j < 16; j++) vv[j] *= inv;
#pragma unroll
        for (int j = 0; j < 4; j++) *(float4*)(rp + 4 * j) = *(float4*)(vv + 4 * j);
    }
    __syncthreads();

    // w[k] = sum_i L[i][k]; stash 1/(w+eps).  Optionally persist L.
    if (tid < 64) {
        float s = 0.f;
#pragma unroll 8
        for (int i = 0; i < 64; i++) s += Ls[i * KL_PL + tid];
        wsh[tid] = 1.0f / (s + EPS_);
    }
    if (writeL) {
        float* Lg = g_LBUF + ((size_t)bh * BB_ + l) * M_ * M_;
        for (int idx = tid; idx < 64 * 16; idx += 256) {
            int i = idx >> 4, k4 = idx & 15;
            float* p = Ls + i * KL_PL + k4 * 4;
            *(float4*)(Lg + idx * 4) = make_float4(p[0], p[1], p[2], p[3]);
        }
    }
    __syncthreads();

    // GEMM2: Qbar[k][d] = sum_i L[i][k] * Q[i][d]   (A = L^T read transposed)
    float acc2[4][4];
#pragma unroll
    for (int nt = 0; nt < 4; nt++)
#pragma unroll
        for (int e = 0; e < 4; e++) acc2[nt][e] = 0.f;

#pragma unroll
    for (int s = 0; s < 8; s++) {
        int i0 = s * 8;
        uint32_t a0 = f2tf(Ls[(i0 + t    ) * KL_PL + m0 + g    ]);
        uint32_t a1 = f2tf(Ls[(i0 + t    ) * KL_PL + m0 + g + 8]);
        uint32_t a2 = f2tf(Ls[(i0 + t + 4) * KL_PL + m0 + g    ]);
        uint32_t a3 = f2tf(Ls[(i0 + t + 4) * KL_PL + m0 + g + 8]);
#pragma unroll
        for (int nt = 0; nt < 4; nt++) {
            int n0 = wc * 32 + nt * 8;
            uint32_t b0 = f2tf(Qs[(i0 + t    ) * KL_PQ + n0 + g]);
            uint32_t b1 = f2tf(Qs[(i0 + t + 4) * KL_PQ + n0 + g]);
            mma8(acc2[nt], a0, a1, a2, a3, b0, b1);
        }
    }

    float* Qbg = g_QBAR + (size_t)bh * M_ * BB_ * D_ + (size_t)l * D_;
    float w0 = wsh[m0 + g], w1 = wsh[m0 + g + 8];
#pragma unroll
    for (int nt = 0; nt < 4; nt++) {
        int n0 = wc * 32 + nt * 8;
        *(float2*)(Qbg + (size_t)(m0 + g    ) * BB_ * D_ + n0 + 2 * t) =
            make_float2(acc2[nt][0] * w0, acc2[nt][1] * w0);
        *(float2*)(Qbg + (size_t)(m0 + g + 8) * BB_ * D_ + n0 + 2 * t) =
            make_float2(acc2[nt][2] * w1, acc2[nt][3] * w1);
    }
}

// ---------------------------------------------------------------------------
// Kernel 3 (tensor): per (bh, k):
//   S = scale * Qbar_k (128x64) @ K_k^T ; R = softmax_{l'}(S)
//   Kbar = R @ K_k   (or Vbar = R @ V_k on last iter)
// grid (64, 64), 256 threads.  Scores held in regs; Rs aliases Qbs region.
// ---------------------------------------------------------------------------
#define KR_PQ 68
#define KR_PK 68
#define KR_PR 132
#define KR_SMEM_FLOATS (BB_*KR_PR + BB_*KR_PK)
#define KR_SMEM_BYTES  (KR_SMEM_FLOATS * 4)

__global__ __launch_bounds__(256, 2)
void kr_kernel(const float* __restrict__ K, const float* __restrict__ V, int last)
{
    extern __shared__ float sm[];
    float* Rs  = sm;                  // [128][132]; prefix doubles as Qbs[128][68]
    float* Qbs = sm;
    float* Ks  = sm + BB_ * KR_PR;    // [128][68]  K_k, overwritten by V_k on last

    int k  = blockIdx.x;
    int bh = blockIdx.y;
    int tid = threadIdx.x;
    int lane = tid & 31, wid = tid >> 5;
    int g = lane >> 2, t = lane & 3;

    const float* Qbg = g_QBAR + ((size_t)bh * M_ + k) * BB_ * D_;
    for (int idx = tid; idx < BB_ * 16; idx += 256) {
        int ll = idx >> 4, d4 = idx & 15;
        float4 v = *(const float4*)(Qbg + idx * 4);
        float* p = Qbs + ll * KR_PQ + d4 * 4;
        p[0] = v.x; p[1] = v.y; p[2] = v.z; p[3] = v.w;
    }
    const float* Kg = K + ((size_t)bh * N_ + (size_t)k * BB_) * D_;
    for (int idx = tid; idx < BB_ * 16; idx += 256) {
        int ll = idx >> 4, d4 = idx & 15;
        float4 v = *(const float4*)(Kg + idx * 4);
        float* p = Ks + ll * KR_PK + d4 * 4;
        p[0] = v.x; p[1] = v.y; p[2] = v.z; p[3] = v.w;
    }
    __syncthreads();

    int wr = wid >> 1, wc = wid & 1;

    // GEMM1: S[l][l'] (128x128), accum fully in registers (64 f32/lane)
    float acc1[2][8][4];
#pragma unroll
    for (int mt = 0; mt < 2; mt++)
#pragma unroll
        for (int nt = 0; nt < 8; nt++)
#pragma unroll
            for (int e = 0; e < 4; e++) acc1[mt][nt][e] = 0.f;

#pragma unroll
    for (int s = 0; s < 8; s++) {
        int d0 = s * 8;
        uint32_t a[2][4];
#pragma unroll
        for (int mt = 0; mt < 2; mt++) {
            int m0 = wr * 32 + mt * 16;
            a[mt][0] = f2tf(Qbs[(m0 + g    ) * KR_PQ + d0 + t    ]);
            a[mt][1] = f2tf(Qbs[(m0 + g + 8) * KR_PQ + d0 + t    ]);
            a[mt][2] = f2tf(Qbs[(m0 + g    ) * KR_PQ + d0 + t + 4]);
            a[mt][3] = f2tf(Qbs[(m0 + g + 8) * KR_PQ + d0 + t + 4]);
        }
#pragma unroll
        for (int nt = 0; nt < 8; nt++) {
            int n0 = wc * 64 + nt * 8;
            uint32_t b0 = f2tf(Ks[(n0 + g) * KR_PK + d0 + t    ]);
            uint32_t b1 = f2tf(Ks[(n0 + g) * KR_PK + d0 + t + 4]);
            mma8(acc1[0][nt], a[0][0], a[0][1], a[0][2], a[0][3], b0, b1);
            mma8(acc1[1][nt], a[1][0], a[1][1], a[1][2], a[1][3], b0, b1);
        }
    }
    __syncthreads();   // all Qbs reads done before scores overwrite the region

    // scaled scores -> Rs
#pragma unroll
    for (int mt = 0; mt < 2; mt++) {
        int m0 = wr * 32 + mt * 16;
#pragma unroll
        for (int nt = 0; nt < 8; nt++) {
            int n0 = wc * 64 + nt * 8;
            Rs[(m0 + g    ) * KR_PR + n0 + 2 * t    ] = acc1[mt][nt][0] * SCALE_;
            Rs[(m0 + g    ) * KR_PR + n0 + 2 * t + 1] = acc1[mt][nt][1] * SCALE_;
            Rs[(m0 + g + 8) * KR_PR + n0 + 2 * t    ] = acc1[mt][nt][2] * SCALE_;
            Rs[(m0 + g + 8) * KR_PR + n0 + 2 * t + 1] = acc1[mt][nt][3] * SCALE_;
        }
    }
    // On last iter: V replaces K as the second-GEMM operand (K reads are done)
    if (last) {
        const float* Vg = V + ((size_t)bh * N_ + (size_t)k * BB_) * D_;
        for (int idx = tid; idx < BB_ * 16; idx += 256) {
            int ll = idx >> 4, d4 = idx & 15;
            float4 v = *(const float4*)(Vg + idx * 4);
            float* p = Ks + ll * KR_PK + d4 * 4;
            p[0] = v.x; p[1] = v.y; p[2] = v.z; p[3] = v.w;
        }
    }
    __syncthreads();

    // softmax over l': 2 threads per row (64 elements each), shfl pair
    {
        int row = tid >> 1, h = tid & 1;
        float* rp = Rs + row * KR_PR + h * 64;
        float vv[64];
#pragma unroll
        for (int j = 0; j < 16; j++) *(float4*)(vv + 4 * j) = *(float4*)(rp + 4 * j);
        float mx = -1e30f;
#pragma unroll
        for (int j = 0; j < 64; j++) mx = fmaxf(mx, vv[j]);
        mx = fmaxf(mx, __shfl_xor_sync(0xffffffffu, mx, 1));
        float ssum = 0.f;
#pragma unroll
        for (int j = 0; j < 64; j++) { vv[j] = __expf(vv[j] - mx); ssum += vv[j]; }
        ssum += __shfl_xor_sync(0xffffffffu, ssum, 1);
        float inv = 1.0f / ssum;
#pragma unroll
        for (int j = 0; j < 64; j++) vv[j] *= inv;
#pragma unroll
        for (int j = 0; j < 16; j++) *(float4*)(rp + 4 * j) = *(float4*)(vv + 4 * j);
    }
    __syncthreads();

    // GEMM2: out[l][d] = sum_{l'} R[l][l'] * Op[l'][d]
    float acc2[2][4][4];
#pragma unroll
    for (int mt = 0; mt < 2; mt++)
#pragma unroll
        for (int nt = 0; nt < 4; nt++)
#pragma unroll
            for (int e = 0; e < 4; e++) acc2[mt][nt][e] = 0.f;

#pragma unroll
    for (int s = 0; s < 16; s++) {
        int kk0 = s * 8;
        uint32_t a[2][4];
#pragma unroll
        for (int mt = 0; mt < 2; mt++) {
            int m0 = wr * 32 + mt * 16;
            a[mt][0] = f2tf(Rs[(m0 + g    ) * KR_PR + kk0 + t    ]);
            a[mt][1] = f2tf(Rs[(m0 + g + 8) * KR_PR + kk0 + t    ]);
            a[mt][2] = f2tf(Rs[(m0 + g    ) * KR_PR + kk0 + t + 4]);
            a[mt][3] = f2tf(Rs[(m0 + g + 8) * KR_PR + kk0 + t + 4]);
        }
#pragma unroll
        for (int nt = 0; nt < 4; nt++) {
            int n0 = wc * 32 + nt * 8;
            uint32_t b0 = f2tf(Ks[(kk0 + t    ) * KR_PK + n0 + g]);
            uint32_t b1 = f2tf(Ks[(kk0 + t + 4) * KR_PK + n0 + g]);
            mma8(acc2[0][nt], a[0][0], a[0][1], a[0][2], a[0][3], b0, b1);
            mma8(acc2[1][nt], a[1][0], a[1][1], a[1][2], a[1][3], b0, b1);
        }
    }

    float* dst = (last ? g_VBAR : g_KBAR) + ((size_t)bh * BB_ * M_ + (size_t)k) * D_;
#pragma unroll
    for (int mt = 0; mt < 2; mt++) {
        int m0 = wr * 32 + mt * 16;
#pragma unroll
        for (int nt = 0; nt < 4; nt++) {
            int n0 = wc * 32 + nt * 8;
            *(float2*)(dst + (size_t)(m0 + g    ) * M_ * D_ + n0 + 2 * t) =
                make_float2(acc2[mt][nt][0], acc2[mt][nt][1]);
            *(float2*)(dst + (size_t)(m0 + g + 8) * M_ * D_ + n0 + 2 * t) =
                make_float2(acc2[mt][nt][2], acc2[mt][nt][3]);
        }
    }
}

// ---------------------------------------------------------------------------
// Kernel 4 (tensor): per (bh, l): out[i][d] = sum_k L[i][k] * Vbar[k][d]
// grid (128, 64), 256 threads
// ---------------------------------------------------------------------------
#define OUT_PL 68
#define OUT_PV 72
__global__ __launch_bounds__(256, 4)
void out_kernel(float* __restrict__ O)
{
    __shared__ float Ls[64 * OUT_PL];
    __shared__ float Vbs[64 * OUT_PV];

    int l  = blockIdx.x;
    int bh = blockIdx.y;
    int tid = threadIdx.x;
    int lane = tid & 31, wid = tid >> 5;
    int g = lane >> 2, t = lane & 3;

    const float* Lg = g_LBUF + ((size_t)bh * BB_ + l) * M_ * M_;
    for (int idx = tid; idx < 64 * 16; idx += 256) {
        int i = idx >> 4, k4 = idx & 15;
        float4 v = *(const float4*)(Lg + idx * 4);
        float* p = Ls + i * OUT_PL + k4 * 4;
        p[0] = v.x; p[1] = v.y; p[2] = v.z; p[3] = v.w;
    }
    const float* Vg = g_VBAR + ((size_t)bh * BB_ + l) * M_ * D_;
    for (int idx = tid; idx < 64 * 16; idx += 256) {
        int kk = idx >> 4, d4 = idx & 15;
        float4 v = *(const float4*)(Vg + idx * 4);
        float* p = Vbs + kk * OUT_PV + d4 * 4;
        p[0] = v.x; p[1] = v.y; p[2] = v.z; p[3] = v.w;
    }
    __syncthreads();

    int wr = wid >> 1, wc = wid & 1;
    int m0 = wr * 16;

    float acc[4][4];
#pragma unroll
    for (int nt = 0; nt < 4; nt++)
#pragma unroll
        for (int e = 0; e < 4; e++) acc[nt][e] = 0.f;

#pragma unroll
    for (int s = 0; s < 8; s++) {
        int k0 = s * 8;
        uint32_t a0 = f2tf(Ls[(m0 + g    ) * OUT_PL + k0 + t    ]);
        uint32_t a1 = f2tf(Ls[(m0 + g + 8) * OUT_PL + k0 + t    ]);
        uint32_t a2 = f2tf(Ls[(m0 + g    ) * OUT_PL + k0 + t + 4]);
        uint32_t a3 = f2tf(Ls[(m0 + g + 8) * OUT_PL + k0 + t + 4]);
#pragma unroll
        for (int nt = 0; nt < 4; nt++) {
            int n0 = wc * 32 + nt * 8;
            uint32_t b0 = f2tf(Vbs[(k0 + t    ) * OUT_PV + n0 + g]);
            uint32_t b1 = f2tf(Vbs[(k0 + t + 4) * OUT_PV + n0 + g]);
            mma8(acc[nt], a0, a1, a2, a3, b0, b1);
        }
    }

    float* Og = O + (size_t)bh * N_ * D_ + (size_t)l * D_;
#pragma unroll
    for (int nt = 0; nt < 4; nt++) {
        int n0 = wc * 32 + nt * 8;
        *(float2*)(Og + (size_t)(m0 + g    ) * BB_ * D_ + n0 + 2 * t) =
            make_float2(acc[nt][0], acc[nt][1]);
        *(float2*)(Og + (size_t)(m0 + g + 8) * BB_ * D_ + n0 + 2 * t) =
            make_float2(acc[nt][2], acc[nt][3]);
    }
}

// ---------------------------------------------------------------------------
extern "C" void kernel_launch(void* const* d_in, const int* in_sizes, int n_in,
                              void* d_out, int out_size)
{
    const float* Q = (const float*)d_in[0];
    const float* K = (const float*)d_in[1];
    const float* V = (const float*)d_in[2];
    float* O = (float*)d_out;

    // Attribute sets (not stream ops; capture-safe, idempotent)
    cudaFuncSetAttribute(kl_kernel, cudaFuncAttributeMaxDynamicSharedMemorySize,
                         KL_SMEM_BYTES);
    cudaFuncSetAttribute(kr_kernel, cudaFuncAttributeMaxDynamicSharedMemorySize,
                         KR_SMEM_BYTES);

    dim3 blk(256);
    init_kbar_kernel<<<dim3(M_, BH_), blk>>>(K);
    for (int t = 0; t < NSTEPS_; t++) {
        int lastFlag = (t == NSTEPS_ - 1) ? 1 : 0;
        kl_kernel<<<dim3(BB_, BH_), blk, KL_SMEM_BYTES>>>(Q, lastFlag);
        kr_kernel<<<dim3(M_, BH_), blk, KR_SMEM_BYTES>>>(K, V, lastFlag);
    }
    out_kernel<<<dim3(BB_, BH_), blk>>>(O);
}